// round 8
// baseline (speedup 1.0000x reference)
#include <cuda_runtime.h>
#include <math_constants.h>

#define EPS_WH 1e-07f
#define MAX_WH 10000000.0f
#define THREADS 256
#define STAGES 6              // cp.async ring depth (24 KB smem)

// Scratch: per-block argmax keys + completion counter.
__device__ unsigned long long g_keys[4096];
__device__ int g_count;       // zero-initialized; reset by last block each run

__device__ __forceinline__ float clip_wh(float v) {
    return fminf(fmaxf(v, EPS_WH), MAX_WH);
}

__device__ __forceinline__ unsigned int f2sortable(float f) {
    unsigned int u = __float_as_uint(f);
    return (u & 0x80000000u) ? ~u : (u | 0x80000000u);
}

__device__ __forceinline__ unsigned int smem_u32(const void* p) {
    unsigned int a;
    asm("{ .reg .u64 t; cvta.to.shared.u64 t, %1; cvt.u32.u64 %0, t; }"
        : "=r"(a) : "l"(p));
    return a;
}

__device__ __forceinline__ void cp_async16(unsigned int dst, const void* src) {
    asm volatile("cp.async.cg.shared.global [%0], [%1], 16;"
                 :: "r"(dst), "l"(src));
}
__device__ __forceinline__ void cp_commit() {
    asm volatile("cp.async.commit_group;");
}
template <int N>
__device__ __forceinline__ void cp_wait() {
    asm volatile("cp.async.wait_group %0;" :: "n"(N));
}

__device__ __forceinline__ float gwd_loss_one(
    const float* __restrict__ ab, const float* __restrict__ trig,
    const float* __restrict__ center, const float* __restrict__ target,
    int b, int idx, int HW)
{
    const float* abb = ab   + (size_t)b * 2 * HW;
    const float* tgb = trig + (size_t)b * 2 * HW;
    float a1    = __ldg(&abb[idx]);
    float a2    = __ldg(&abb[HW + idx]);
    float sin2A = __ldg(&tgb[idx]);
    float cos2A = __ldg(&tgb[HW + idx]);

    // deg roundtrip in the reference is the identity; stay in radians
    float r_p = 0.5f * atan2f(sin2A, cos2A);
    float xp = center[2 * b], yp = center[2 * b + 1];
    float s1p = 0.5f * clip_wh(2.0f * a1);
    float s2p = 0.5f * clip_wh(2.0f * a2);
    float cp = cosf(r_p), sp = sinf(r_p);

    float xt = target[5 * b + 0];
    float yt = target[5 * b + 1];
    float s1t = 0.5f * clip_wh(target[5 * b + 2]);
    float s2t = 0.5f * clip_wh(target[5 * b + 3]);
    float r_t = target[5 * b + 4] * (CUDART_PI_F / 180.0f);
    float ct = cosf(r_t), st = sinf(r_t);

    float dx = xp - xt, dy = yp - yt;
    float xy_dist = dx * dx + dy * dy;

    float sp1_2 = s1p * s1p, sp2_2 = s2p * s2p;
    float st1_2 = s1t * s1t, st2_2 = s2t * s2t;

    float Ap = sp1_2 * cp * cp + sp2_2 * sp * sp;
    float Bp = sp1_2 * sp * sp + sp2_2 * cp * cp;
    float Cp = (sp1_2 - sp2_2) * cp * sp;

    float At = st1_2 * ct * ct + st2_2 * st * st;
    float Bt = st1_2 * st * st + st2_2 * ct * ct;
    float Ct = (st1_2 - st2_2) * ct * st;

    float tr_pt = Ap * At + Bp * Bt + 2.0f * Cp * Ct;
    float det_sqrt = sqrtf(fmaxf(s1p * s2p * s1t * s2t, 0.0f));

    float whr = sp1_2 + sp2_2 + st1_2 + st2_2
              - 2.0f * sqrtf(fmaxf(tr_pt + 2.0f * det_sqrt, 0.0f));

    float dist = fmaxf(xy_dist + whr, 0.0f);
    return 1.0f - 1.0f / (1.0f + dist);
}

// One block per batch row. cp.async ring: MLP lives in the LSU, not the
// register file -> low regs -> 8 blocks/SM. Each thread consumes only its
// own copied float4, so the pipeline loop has NO block barriers.
__global__ void __launch_bounds__(THREADS)
gwd_fused_kernel(const float* __restrict__ hm,
                 const float* __restrict__ ab,
                 const float* __restrict__ trig,
                 const float* __restrict__ center,
                 const float* __restrict__ target,
                 float* __restrict__ out,
                 int HW, int B)
{
    const int b = blockIdx.x;
    const int t = threadIdx.x;

    __shared__ float4 buf[STAGES][THREADS];

    const float4* hm4 = reinterpret_cast<const float4*>(hm + (size_t)b * HW);
    const int NITER = HW >> 10;   // HW / (THREADS*4) = 16

    const unsigned int sdst = smem_u32(&buf[0][t]);
    const unsigned int sstride = sizeof(float4) * THREADS;

    // Prologue: issue STAGES-1 tile copies, one commit group each.
    #pragma unroll
    for (int s = 0; s < STAGES - 1; s++) {
        cp_async16(sdst + s * sstride, &hm4[s * THREADS + t]);
        cp_commit();
    }

    float best = -CUDART_INF_F;
    int bidx = 0;

    for (int i = 0; i < NITER; i++) {
        // Issue copy for iteration i+STAGES-1 (group number stays aligned
        // by committing every iteration, even when past the end).
        int nx = i + STAGES - 1;
        if (nx < NITER)
            cp_async16(sdst + (nx % STAGES) * sstride, &hm4[nx * THREADS + t]);
        cp_commit();

        // Wait until <= STAGES-1 groups pending -> group i complete.
        cp_wait<STAGES - 1>();

        float4 v = buf[i % STAGES][t];
        int base = (i * THREADS + t) << 2;

        float m = fmaxf(fmaxf(v.x, v.y), fmaxf(v.z, v.w));
        int idx4 = (v.z == m) ? (base + 2) : (base + 3);
        idx4     = (v.y == m) ? (base + 1) : idx4;
        idx4     = (v.x == m) ?  base      : idx4;

        bidx = (m > best) ? idx4 : bidx;   // strict > keeps earliest i on ties
        best = fmaxf(best, m);
    }

    // Pack (sortable value | ~idx): max picks max value, ties -> smallest idx.
    unsigned long long key =
        ((unsigned long long)f2sortable(best) << 32) |
        (unsigned long long)(unsigned int)(~bidx);

    #pragma unroll
    for (int off = 16; off > 0; off >>= 1) {
        unsigned long long o = __shfl_xor_sync(0xffffffffu, key, off);
        key = (o > key) ? o : key;
    }

    __shared__ unsigned long long skey[THREADS / 32];
    if ((t & 31) == 0) skey[t >> 5] = key;
    __syncthreads();
    if (t < 32) {
        unsigned long long k = (t < THREADS / 32) ? skey[t] : 0ull;
        #pragma unroll
        for (int off = 4; off > 0; off >>= 1) {
            unsigned long long o = __shfl_xor_sync(0xffffffffu, k, off);
            k = (o > k) ? o : k;
        }
        if (t == 0) g_keys[b] = k;
    }

    // ---- last-block-done: all epilogues + deterministic mean ----
    __shared__ bool amLast;
    __syncthreads();
    if (t == 0) {
        __threadfence();
        amLast = (atomicAdd(&g_count, 1) == gridDim.x - 1);
    }
    __syncthreads();

    if (amLast) {
        __threadfence();  // make peer g_keys writes visible

        float acc = 0.0f;
        for (int bb = t; bb < B; bb += THREADS) {
            unsigned long long kk = __ldcg(&g_keys[bb]);
            int idx = (int)(~((unsigned int)(kk & 0xffffffffu)));
            acc += gwd_loss_one(ab, trig, center, target, bb, idx, HW);
        }

        __shared__ float sh[THREADS];
        sh[t] = acc;
        __syncthreads();
        #pragma unroll
        for (int s = THREADS / 2; s > 0; s >>= 1) {
            if (t < s) sh[t] += sh[t + s];
            __syncthreads();
        }
        if (t == 0) {
            out[0] = sh[0] / (float)B;
            g_count = 0;  // reset for next graph replay
        }
    }
}

extern "C" void kernel_launch(void* const* d_in, const int* in_sizes, int n_in,
                              void* d_out, int out_size)
{
    const float* hm     = (const float*)d_in[0];  // (B,1,H,W)
    const float* ab     = (const float*)d_in[1];  // (B,2,H,W)
    const float* trig   = (const float*)d_in[2];  // (B,2,H,W)
    const float* center = (const float*)d_in[3];  // (B,2)
    const float* target = (const float*)d_in[4];  // (B,5)
    float* out = (float*)d_out;

    const int B  = in_sizes[4] / 5;
    const int HW = in_sizes[0] / B;   // 16384

    gwd_fused_kernel<<<B, THREADS>>>(hm, ab, trig, center, target, out, HW, B);
}